// round 15
// baseline (speedup 1.0000x reference)
#include <cuda_runtime.h>
#include <cuda_fp16.h>
#include <cstdint>

#define BH  32
#define T   8192
#define DH  64
#define BSZ 128
#define NB  64
#define HH  4

// ---------------- scratch ----------------
__device__ float g_qsum  [BH*NB*DH];
__device__ float g_ksum  [BH*NB*DH];
__device__ float g_W     [BH*NB*DH];
__device__ float g_qfirst[BH*NB*DH];
__device__ int   g_sel   [BH*NB];
__device__ float g_wgt   [BH*NB];
__device__ int   g_cnt   [BH];          // zero-initialized; self-resetting

__device__ __forceinline__ int rot_idx(int g, bool special) {
    return special ? ((g + BSZ - 1) & (T - 1)) : g;
}
__device__ __forceinline__ uint32_t pack_h2(float a, float b) {
    __half2 h = __floats2half2_rn(a, b);
    return *reinterpret_cast<uint32_t*>(&h);
}
__device__ __forceinline__ uint32_t smem_u32(const void* p) {
    uint32_t a;
    asm("{ .reg .u64 t; cvta.to.shared.u64 t, %1; cvt.u32.u64 %0, t; }"
        : "=r"(a) : "l"(p));
    return a;
}
__device__ __forceinline__ void mma_f16(float c[4], uint32_t a0, uint32_t a1,
                                        uint32_t a2, uint32_t a3,
                                        uint32_t b0, uint32_t b1) {
    asm("mma.sync.aligned.m16n8k16.row.col.f32.f16.f16.f32 "
        "{%0,%1,%2,%3}, {%4,%5,%6,%7}, {%8,%9}, {%0,%1,%2,%3};"
        : "+f"(c[0]), "+f"(c[1]), "+f"(c[2]), "+f"(c[3])
        : "r"(a0), "r"(a1), "r"(a2), "r"(a3), "r"(b0), "r"(b1));
}
__device__ __forceinline__ void ldsm_x4_t(uint32_t& r0, uint32_t& r1,
                                          uint32_t& r2, uint32_t& r3,
                                          uint32_t addr) {
    asm volatile("ldmatrix.sync.aligned.m8n8.x4.trans.shared.b16 "
                 "{%0,%1,%2,%3}, [%4];"
                 : "=r"(r0), "=r"(r1), "=r"(r2), "=r"(r3) : "r"(addr));
}

// half2-pair permuted position for K (vectorized QK B fetch)
#define HPOS(p) ((((p) & 3) * 8) + ((p) >> 2))
#define HSTR 36                         // b32 per fp16 row (32 + 4 pad)
#define KHOFF 0
#define VHOFF (256 * HSTR)              // 9216 b32
#define SMEM_B32 (512 * HSTR)           // 18432 b32 = 73728 B

// K2 (route) dynamic smem float-offsets
#define K2_SQ  0
#define K2_SK  4160
#define K2_LG  8320
#define K2_H   12480
#define K2_GQ  12544
#define K2_GK  12800
#define K2_SMEM_F 13056                 // 52224 B (also holds K1 scratch)
// K1 scratch (overlaps K2 region; consumed before route starts)
#define K1_RINV 0                       // 128 floats
#define K1_SQ   128                     // 4*64
#define K1_RK   384
#define K1_WL   640
#define K1_HQ   896                     // 4

// ---------------- K1+K2 fused: per-bucket stats, then last block routes ----
__global__ void __launch_bounds__(256)
k_stats_route(const float* __restrict__ q, const float* __restrict__ k)
{
    extern __shared__ float s2[];
    __shared__ bool s_last;
    int blk = blockIdx.x;          // bh*NB + u
    int bh = blk >> 6, u = blk & 63;
    int tx = threadIdx.x;          // 0..255
    int d  = tx & 63, qd = tx >> 6;
    bool special = ((bh & 7) >= HH);
    const float* qb = q + (size_t)bh * T * DH;
    const float* kb = k + (size_t)bh * T * DH;
    int base = u * BSZ;

    // ---- K1: bucket stats, j-parallel over 4 quarters ----
    if (tx < BSZ) s2[K1_RINV + tx] = 1.0f / (float)(base + tx + 1);
    __syncthreads();

    float sumq = 0.f, rk = 0.f, wl = 0.f, hq = 0.f, qfirst = 0.f;
    int j0 = qd * 32;
    #pragma unroll 8
    for (int jj = 0; jj < 32; ++jj) {
        int j = j0 + jj;
        int src = rot_idx(base + j, special);
        float qv = qb[(size_t)src * DH + d];
        float kv = kb[(size_t)src * DH + d];
        if (jj == 0 && qd == 0) qfirst = qv;
        sumq += qv;
        rk += kv;
        float ri = s2[K1_RINV + j];
        wl = fmaf(rk, ri, wl);
        hq += ri;
    }
    s2[K1_SQ + qd * 64 + d] = sumq;
    s2[K1_RK + qd * 64 + d] = rk;
    s2[K1_WL + qd * 64 + d] = wl;
    if (d == 0) s2[K1_HQ + qd] = hq;
    __syncthreads();

    if (qd == 0) {
        float r0 = rk;
        float r1 = s2[K1_RK + 64 + d], r2 = s2[K1_RK + 128 + d], r3 = s2[K1_RK + 192 + d];
        float W = wl
                + fmaf(r0,           s2[K1_HQ + 1], s2[K1_WL + 64 + d])
                + fmaf(r0 + r1,      s2[K1_HQ + 2], s2[K1_WL + 128 + d])
                + fmaf(r0 + r1 + r2, s2[K1_HQ + 3], s2[K1_WL + 192 + d]);
        float runk = r0 + r1 + r2 + r3;
        float sq = sumq + s2[K1_SQ + 64 + d] + s2[K1_SQ + 128 + d] + s2[K1_SQ + 192 + d];
        int o = blk * DH + d;
        g_qsum[o] = sq; g_ksum[o] = runk; g_W[o] = W; g_qfirst[o] = qfirst;
    }
    __threadfence();
    __syncthreads();

    // ---- elect last block of this bh ----
    if (tx == 0) {
        int old = atomicAdd(&g_cnt[bh], 1);
        s_last = (old == NB - 1);
    }
    __syncthreads();
    if (!s_last) return;
    __threadfence();   // acquire: other blocks' g_* writes are visible

    // ---- K2: parallel prefix + routing for this bh ----
    if (qd == 0) {             // H[u]
        int uu = d;
        float hsum = 0.f;
        for (int j = 1; j <= BSZ; ++j) hsum += 1.0f / (float)(uu * BSZ + j);
        s2[K2_H + uu] = hsum;
    }

    // segment sums (buckets [16qd, 16qd+16))
    float sq_ = 0.f, sk_ = 0.f;
    #pragma unroll 4
    for (int i = 0; i < 16; ++i) {
        int o = (bh * NB + qd * 16 + i) * DH + d;
        sq_ += g_qsum[o]; sk_ += g_ksum[o];
    }
    s2[K2_GQ + qd * 64 + d] = sq_;
    s2[K2_GK + qd * 64 + d] = sk_;
    __syncthreads();

    float baseQ = 0.f, baseK = 0.f;
    for (int q2 = 0; q2 < qd; ++q2) {
        baseQ += s2[K2_GQ + q2 * 64 + d];
        baseK += s2[K2_GK + q2 * 64 + d];
    }
    for (int i = 0; i < 16; ++i) {
        int uu = qd * 16 + i;
        int o = (bh * NB + uu) * DH + d;
        s2[K2_SQ + uu * 65 + d] = (baseQ + g_qfirst[o]) / (float)(uu * BSZ + 1);
        s2[K2_SK + uu * 65 + d] = baseK * s2[K2_H + uu] + g_W[o];
        baseQ += g_qsum[o]; baseK += g_ksum[o];
    }
    __syncthreads();

    // logits: thread (u=d, qd) handles vv in {1+qd, 5+qd, ...} <= u
    {
        int uu = d;
        if (qd == 0) s2[K2_LG + uu * 65] = 0.f;   // null column
        const float* squ = s2 + K2_SQ + uu * 65;
        for (int vv = 1 + qd; vv <= uu; vv += 4) {
            const float* skv = s2 + K2_SK + (vv - 1) * 65;
            float s = 0.f;
            #pragma unroll 8
            for (int dd = 0; dd < DH; ++dd) s += squ[dd] * skv[dd];
            s2[K2_LG + uu * 65 + vv] = s * 0.125f;
        }
    }
    __syncthreads();

    // scan: one thread per u; thread 0 also resets the counter
    if (tx == 0) g_cnt[bh] = 0;
    if (tx < NB) {
        int uu = tx;
        if (uu == 0) { g_sel[bh * NB] = 0; g_wgt[bh * NB] = 0.f; return; }
        const float* lg = s2 + K2_LG + uu * 65;
        float m = 0.f;
        for (int vv = 1; vv <= uu; ++vv) m = fmaxf(m, lg[vv]);
        float ssum = expf(0.f - m);
        for (int vv = 1; vv <= uu; ++vv) ssum += expf(lg[vv] - m);
        int best = 0; float bl = lg[0];
        for (int vv = 1; vv <= uu - 1; ++vv)
            if (lg[vv] > bl) { bl = lg[vv]; best = vv; }
        g_sel[bh * NB + uu] = best;
        g_wgt[bh * NB + uu] = expf(bl - m) / ssum;
    }
}

// ---------------- K4: full-fp16 MMA attention tile (v7 = R13) ----------------
__global__ void __launch_bounds__(256, 3)
k_attn_mma(const float* __restrict__ q, const float* __restrict__ k,
           const float* __restrict__ v, const float* __restrict__ nk,
           const float* __restrict__ nv, float* __restrict__ out)
{
    extern __shared__ uint32_t sh[];
    uint32_t* Kh = sh + KHOFF;           // 256 rows x HSTR (fp16 permuted)
    uint32_t* Vh = sh + VHOFF;           // 256 rows x HSTR (fp16 plain)
    uint32_t* Qh = Vh;                   // Q staging reuses V region

    int tid  = threadIdx.x;
    int wid  = tid >> 5, lane = tid & 31;
    int g    = lane >> 2, t = lane & 3;
    int R0   = wid * 16;
    int i0   = R0 + g, i1 = R0 + g + 8;

    int blk = blockIdx.x, bh = blk >> 6, u = blk & 63, h = bh & 7;
    bool special = (h >= HH);
    bool smask   = special && (u == NB - 1);

    int   selv = g_sel[bh * NB + u];
    float w    = g_wgt[bh * NB + u];
    const float* qb = q + (size_t)bh * T * DH;
    const float* kb = k + (size_t)bh * T * DH;
    const float* vb = v + (size_t)bh * T * DH;

    // ---- stage Q (x0.125, fp16 HPOS-permuted) into V region ----
    for (int idx = tid; idx < 128 * 16; idx += 256) {
        int r = idx >> 4, c0 = (idx & 15) * 4;
        int srcQ = rot_idx(u * BSZ + r, special);
        float4 qq = reinterpret_cast<const float4*>(qb + (size_t)srcQ * DH)[c0 >> 2];
        int p0 = c0 >> 1;
        Qh[r * HSTR + HPOS(p0)]     = pack_h2(qq.x * 0.125f, qq.y * 0.125f);
        Qh[r * HSTR + HPOS(p0 + 1)] = pack_h2(qq.z * 0.125f, qq.w * 0.125f);
    }
    __syncthreads();

    // ---- extract Q A-fragments (4x ld.128) ----
    uint32_t qA0[8], qA1[8];
    {
        uint4 x;
        x = *reinterpret_cast<uint4*>(&Qh[i0 * HSTR + t * 8]);
        qA0[0] = x.x; qA0[1] = x.y; qA0[2] = x.z; qA0[3] = x.w;
        x = *reinterpret_cast<uint4*>(&Qh[i0 * HSTR + t * 8 + 4]);
        qA0[4] = x.x; qA0[5] = x.y; qA0[6] = x.z; qA0[7] = x.w;
        x = *reinterpret_cast<uint4*>(&Qh[i1 * HSTR + t * 8]);
        qA1[0] = x.x; qA1[1] = x.y; qA1[2] = x.z; qA1[3] = x.w;
        x = *reinterpret_cast<uint4*>(&Qh[i1 * HSTR + t * 8 + 4]);
        qA1[4] = x.x; qA1[5] = x.y; qA1[6] = x.z; qA1[7] = x.w;
    }
    __syncthreads();   // Q reads done before V staging overwrites

    // ---- single-burst stage: K (HPOS) + V (plain) fp16, both phases ----
    for (int idx = tid; idx < 256 * 16; idx += 256) {
        int r = idx >> 4, c0 = (idx & 15) * 4;
        float4 kk, vv;
        if (r < 128) {
            if (selv == 0) {
                kk = reinterpret_cast<const float4*>(nk + h * DH)[c0 >> 2];
                vv = reinterpret_cast<const float4*>(nv + h * DH)[c0 >> 2];
            } else {
                int srcA = rot_idx((selv - 1) * BSZ + r, special);
                kk = reinterpret_cast<const float4*>(kb + (size_t)srcA * DH)[c0 >> 2];
                vv = reinterpret_cast<const float4*>(vb + (size_t)srcA * DH)[c0 >> 2];
            }
            kk.x *= w; kk.y *= w; kk.z *= w; kk.w *= w;
            vv.x *= w; vv.y *= w; vv.z *= w; vv.w *= w;
        } else {
            int srcB = rot_idx(u * BSZ + (r - 128), special);
            kk = reinterpret_cast<const float4*>(kb + (size_t)srcB * DH)[c0 >> 2];
            vv = reinterpret_cast<const float4*>(vb + (size_t)srcB * DH)[c0 >> 2];
        }
        int p0 = c0 >> 1;
        Kh[r * HSTR + HPOS(p0)]     = pack_h2(kk.x, kk.y);
        Kh[r * HSTR + HPOS(p0 + 1)] = pack_h2(kk.z, kk.w);
        Vh[r * HSTR + p0]     = pack_h2(vv.x, vv.y);
        Vh[r * HSTR + p0 + 1] = pack_h2(vv.z, vv.w);
    }
    __syncthreads();   // LAST block sync

    float oacc[8][4];
    #pragma unroll
    for (int n = 0; n < 8; ++n)
        #pragma unroll
        for (int m = 0; m < 4; ++m) oacc[n][m] = 0.f;
    float lsum0 = 0.f, lsum1 = 0.f;

    // ldmatrix lane base: tile = lane>>3 covers j-offset {0,8,16,24}, row = lane&7
    uint32_t vbase;
    {
        int tile = lane >> 3, rr = lane & 7;
        int joff = (tile & 1) * 8 + (tile >> 1) * 16 + rr;
        vbase = smem_u32(Vh) + (uint32_t)(joff * HSTR * 4);
    }

    #define STRIP(PHASE, S, KB)                                               \
    {                                                                         \
        float c4[4][4];                                                       \
        _Pragma("unroll")                                                     \
        for (int n = 0; n < 4; ++n)                                           \
            _Pragma("unroll")                                                 \
            for (int m = 0; m < 4; ++m) c4[n][m] = 0.f;                       \
        /* QK: S[16,32], fp16 m16n8k16 */                                     \
        _Pragma("unroll")                                                     \
        for (int nt = 0; nt < 4; ++nt) {                                      \
            int j = (KB) + (S) * 32 + nt * 8 + g;                             \
            uint4 f1 = *reinterpret_cast<uint4*>(&Kh[j * HSTR + 8 * t]);      \
            uint4 f2 = *reinterpret_cast<uint4*>(&Kh[j * HSTR + 8 * t + 4]);  \
            mma_f16(c4[nt], qA0[0], qA1[0], qA0[1], qA1[1], f1.x, f1.y);      \
            mma_f16(c4[nt], qA0[2], qA1[2], qA0[3], qA1[3], f1.z, f1.w);      \
            mma_f16(c4[nt], qA0[4], qA1[4], qA0[5], qA1[5], f2.x, f2.y);      \
            mma_f16(c4[nt], qA0[6], qA1[6], qA0[7], qA1[7], f2.z, f2.w);      \
        }                                                                     \
        /* epilogue: mask + exp + row-sums */                                 \
        _Pragma("unroll")                                                     \
        for (int nt = 0; nt < 4; ++nt) {                                      \
            int jb = (S) * 32 + nt * 8 + 2 * t;                               \
            _Pragma("unroll")                                                 \
            for (int m = 0; m < 4; ++m) {                                     \
                int row = (m < 2) ? i0 : i1;                                  \
                int jc  = jb + (m & 1);                                       \
                bool ok;                                                      \
                if ((PHASE) == 0) ok = (!smask) || (row == 0);                \
                else ok = smask ? (row == 0 ? (jc == 0)                       \
                                            : (jc >= 1 && jc <= row))         \
                                : (jc <= row);                                \
                float p = ok ? __expf(fminf(c4[nt][m], 80.f)) : 0.f;          \
                if (m < 2) lsum0 += p; else lsum1 += p;                       \
                c4[nt][m] = p;                                                \
            }                                                                 \
        }                                                                     \
        /* P -> fp16 A fragments (accumulator layout == A layout) */          \
        uint32_t pA[8];                                                       \
        pA[0] = pack_h2(c4[0][0], c4[0][1]); pA[1] = pack_h2(c4[0][2], c4[0][3]); \
        pA[2] = pack_h2(c4[1][0], c4[1][1]); pA[3] = pack_h2(c4[1][2], c4[1][3]); \
        pA[4] = pack_h2(c4[2][0], c4[2][1]); pA[5] = pack_h2(c4[2][2], c4[2][3]); \
        pA[6] = pack_h2(c4[3][0], c4[3][1]); pA[7] = pack_h2(c4[3][2], c4[3][3]); \
        /* PV: O[16,64] += P[16,32] * V[32,64], fp16 via ldmatrix.trans */    \
        uint32_t va = vbase + (uint32_t)(((KB) + (S) * 32) * HSTR * 4);       \
        _Pragma("unroll")                                                     \
        for (int nt = 0; nt < 8; ++nt) {                                      \
            uint32_t b0, b1, b2, b3;                                          \
            ldsm_x4_t(b0, b1, b2, b3, va + nt * 16);                          \
            mma_f16(oacc[nt], pA[0], pA[1], pA[2], pA[3], b0, b1);            \
            mma_f16(oacc[nt], pA[4], pA[5], pA[6], pA[7], b2, b3);            \
        }                                                                     \
    }

    // ---- phase A (routed keys, rows 0-127) ----
    {
        int smaxA = (smask && wid > 0) ? -1 : 3;
        for (int s = 0; s <= smaxA; ++s) STRIP(0, s, 0);
    }
    // ---- phase B (own keys, rows 128-255, triangular) ----
    {
        int smaxB = (R0 + 15) >> 5;
        for (int s = 0; s <= smaxB; ++s) STRIP(1, s, 128);
    }
    #undef STRIP

    // ---- row-sum reduction across the 4 lanes of each row group ----
    lsum0 += __shfl_xor_sync(0xFFFFFFFFu, lsum0, 1);
    lsum0 += __shfl_xor_sync(0xFFFFFFFFu, lsum0, 2);
    lsum1 += __shfl_xor_sync(0xFFFFFFFFu, lsum1, 1);
    lsum1 += __shfl_xor_sync(0xFFFFFFFFu, lsum1, 2);
    float inv0 = 1.0f / lsum0;
    float inv1 = 1.0f / lsum1;

    // ---- write O ----
    int gr0 = rot_idx(u * BSZ + i0, special);
    int gr1 = rot_idx(u * BSZ + i1, special);
    float* op0 = out + ((size_t)bh * T + gr0) * DH;
    float* op1 = out + ((size_t)bh * T + gr1) * DH;
    #pragma unroll
    for (int nt = 0; nt < 8; ++nt) {
        int col = nt * 8 + 2 * t;
        *reinterpret_cast<float2*>(op0 + col) =
            make_float2(oacc[nt][0] * inv0, oacc[nt][1] * inv0);
        *reinterpret_cast<float2*>(op1 + col) =
            make_float2(oacc[nt][2] * inv1, oacc[nt][3] * inv1);
    }
}

// ---------------- launch ----------------
extern "C" void kernel_launch(void* const* d_in, const int* in_sizes, int n_in,
                              void* d_out, int out_size)
{
    (void)in_sizes; (void)n_in; (void)out_size;
    const float* q  = (const float*)d_in[0];
    const float* k  = (const float*)d_in[1];
    const float* v  = (const float*)d_in[2];
    const float* nk = (const float*)d_in[3];
    const float* nv = (const float*)d_in[4];
    float* out = (float*)d_out;

    const int smem_attn = SMEM_B32 * 4;          // 73728 B
    const int smem_k1   = K2_SMEM_F * 4;         // 52224 B
    cudaFuncSetAttribute(k_attn_mma,    cudaFuncAttributeMaxDynamicSharedMemorySize, smem_attn);
    cudaFuncSetAttribute(k_stats_route, cudaFuncAttributeMaxDynamicSharedMemorySize, smem_k1);

    k_stats_route<<<BH * NB, 256, smem_k1>>>(q, k);
    k_attn_mma<<<BH * NB, 256, smem_attn>>>(q, k, v, nk, nv, out);
}

// round 16
// speedup vs baseline: 1.1181x; 1.1181x over previous
#include <cuda_runtime.h>
#include <cuda_fp16.h>
#include <cstdint>

#define BH  32
#define T   8192
#define DH  64
#define BSZ 128
#define NB  64
#define HH  4

// ---------------- scratch ----------------
__device__ float g_qsum  [BH*NB*DH];
__device__ float g_ksum  [BH*NB*DH];
__device__ float g_W     [BH*NB*DH];
__device__ float g_qfirst[BH*NB*DH];
__device__ int   g_sel   [BH*NB];
__device__ float g_wgt   [BH*NB];

__device__ __forceinline__ int rot_idx(int g, bool special) {
    return special ? ((g + BSZ - 1) & (T - 1)) : g;
}
__device__ __forceinline__ uint32_t pack_h2(float a, float b) {
    __half2 h = __floats2half2_rn(a, b);
    return *reinterpret_cast<uint32_t*>(&h);
}
__device__ __forceinline__ uint32_t smem_u32(const void* p) {
    uint32_t a;
    asm("{ .reg .u64 t; cvta.to.shared.u64 t, %1; cvt.u32.u64 %0, t; }"
        : "=r"(a) : "l"(p));
    return a;
}
__device__ __forceinline__ void mma_f16(float c[4], uint32_t a0, uint32_t a1,
                                        uint32_t a2, uint32_t a3,
                                        uint32_t b0, uint32_t b1) {
    asm("mma.sync.aligned.m16n8k16.row.col.f32.f16.f16.f32 "
        "{%0,%1,%2,%3}, {%4,%5,%6,%7}, {%8,%9}, {%0,%1,%2,%3};"
        : "+f"(c[0]), "+f"(c[1]), "+f"(c[2]), "+f"(c[3])
        : "r"(a0), "r"(a1), "r"(a2), "r"(a3), "r"(b0), "r"(b1));
}
__device__ __forceinline__ void ldsm_x4_t(uint32_t& r0, uint32_t& r1,
                                          uint32_t& r2, uint32_t& r3,
                                          uint32_t addr) {
    asm volatile("ldmatrix.sync.aligned.m8n8.x4.trans.shared.b16 "
                 "{%0,%1,%2,%3}, [%4];"
                 : "=r"(r0), "=r"(r1), "=r"(r2), "=r"(r3) : "r"(addr));
}

// half2-pair permuted position for K (vectorized QK B fetch)
#define HPOS(p) ((((p) & 3) * 8) + ((p) >> 2))
#define HSTR 36                         // b32 per fp16 row (32 + 4 pad)
#define KHOFF 0
#define VHOFF (256 * HSTR)              // 9216 b32
#define SMEM_B32 (512 * HSTR)           // 18432 b32 = 73728 B

// ---------------- K1: per-bucket stats, j-parallel over 4 quarters --------
__global__ void __launch_bounds__(256)
k_bucket_stats(const float* __restrict__ q, const float* __restrict__ k)
{
    __shared__ float rinv[BSZ];
    __shared__ float s_sq[4][DH];
    __shared__ float s_rk[4][DH];
    __shared__ float s_wl[4][DH];
    __shared__ float s_hq[4];
    int blk = blockIdx.x;          // bh*NB + u
    int bh = blk >> 6, u = blk & 63;
    int tx = threadIdx.x;          // 0..255
    int d  = tx & 63, qd = tx >> 6;
    bool special = ((bh & 7) >= HH);
    const float* qb = q + (size_t)bh * T * DH;
    const float* kb = k + (size_t)bh * T * DH;
    int base = u * BSZ;

    if (tx < BSZ) rinv[tx] = 1.0f / (float)(base + tx + 1);
    __syncthreads();

    float sumq = 0.f, rk = 0.f, wl = 0.f, hq = 0.f, qfirst = 0.f;
    int j0 = qd * 32;
    #pragma unroll 8
    for (int jj = 0; jj < 32; ++jj) {
        int j = j0 + jj;
        int src = rot_idx(base + j, special);
        float qv = qb[(size_t)src * DH + d];
        float kv = kb[(size_t)src * DH + d];
        if (jj == 0 && qd == 0) qfirst = qv;
        sumq += qv;
        rk += kv;
        float ri = rinv[j];
        wl = fmaf(rk, ri, wl);
        hq += ri;
    }
    s_sq[qd][d] = sumq; s_rk[qd][d] = rk; s_wl[qd][d] = wl;
    if (d == 0) s_hq[qd] = hq;
    __syncthreads();

    if (qd == 0) {
        float r0 = rk;
        float r1 = s_rk[1][d], r2 = s_rk[2][d], r3 = s_rk[3][d];
        float W = wl
                + fmaf(r0,           s_hq[1], s_wl[1][d])
                + fmaf(r0 + r1,      s_hq[2], s_wl[2][d])
                + fmaf(r0 + r1 + r2, s_hq[3], s_wl[3][d]);
        float runk = r0 + r1 + r2 + r3;
        float sq = sumq + s_sq[1][d] + s_sq[2][d] + s_sq[3][d];
        int o = blk * DH + d;
        g_qsum[o] = sq; g_ksum[o] = runk; g_W[o] = W; g_qfirst[o] = qfirst;
    }
}

// ---------------- K2: parallel prefix + routing (256 thr/bh) ----------------
#define K2_SQ  0
#define K2_SK  4160
#define K2_LG  8320
#define K2_H   12480
#define K2_GQ  12544
#define K2_GK  12800
#define K2_SMEM_F 13056

__global__ void __launch_bounds__(256)
k_route2()
{
    extern __shared__ float s2[];
    int bh = blockIdx.x;
    int tx = threadIdx.x;
    int d  = tx & 63, qd = tx >> 6;

    if (qd == 0) {             // H[u]
        int u = d;
        float hsum = 0.f;
        for (int j = 1; j <= BSZ; ++j) hsum += 1.0f / (float)(u * BSZ + j);
        s2[K2_H + u] = hsum;
    }

    // segment sums (buckets [16qd, 16qd+16))
    float sq_ = 0.f, sk_ = 0.f;
    #pragma unroll 4
    for (int i = 0; i < 16; ++i) {
        int o = (bh * NB + qd * 16 + i) * DH + d;
        sq_ += g_qsum[o]; sk_ += g_ksum[o];
    }
    s2[K2_GQ + qd * 64 + d] = sq_;
    s2[K2_GK + qd * 64 + d] = sk_;
    __syncthreads();

    float baseQ = 0.f, baseK = 0.f;
    for (int q2 = 0; q2 < qd; ++q2) {
        baseQ += s2[K2_GQ + q2 * 64 + d];
        baseK += s2[K2_GK + q2 * 64 + d];
    }
    for (int i = 0; i < 16; ++i) {
        int uu = qd * 16 + i;
        int o = (bh * NB + uu) * DH + d;
        s2[K2_SQ + uu * 65 + d] = (baseQ + g_qfirst[o]) / (float)(uu * BSZ + 1);
        s2[K2_SK + uu * 65 + d] = baseK * s2[K2_H + uu] + g_W[o];
        baseQ += g_qsum[o]; baseK += g_ksum[o];
    }
    __syncthreads();

    // logits: thread (u=d, qd) handles vv in {1+qd, 5+qd, ...} <= u
    {
        int u = d;
        if (qd == 0) s2[K2_LG + u * 65] = 0.f;   // null column
        const float* squ = s2 + K2_SQ + u * 65;
        for (int vv = 1 + qd; vv <= u; vv += 4) {
            const float* skv = s2 + K2_SK + (vv - 1) * 65;
            float s = 0.f;
            #pragma unroll 8
            for (int dd = 0; dd < DH; ++dd) s += squ[dd] * skv[dd];
            s2[K2_LG + u * 65 + vv] = s * 0.125f;
        }
    }
    __syncthreads();

    // scan: one thread per u
    if (tx < NB) {
        int u = tx;
        if (u == 0) { g_sel[bh * NB] = 0; g_wgt[bh * NB] = 0.f; return; }
        const float* lg = s2 + K2_LG + u * 65;
        float m = 0.f;
        for (int vv = 1; vv <= u; ++vv) m = fmaxf(m, lg[vv]);
        float ssum = expf(0.f - m);
        for (int vv = 1; vv <= u; ++vv) ssum += expf(lg[vv] - m);
        int best = 0; float bl = lg[0];
        for (int vv = 1; vv <= u - 1; ++vv)
            if (lg[vv] > bl) { bl = lg[vv]; best = vv; }
        g_sel[bh * NB + u] = best;
        g_wgt[bh * NB + u] = expf(bl - m) / ssum;
    }
}

// ---------------- K4: full-fp16 MMA attention tile (v9) ----------------
// R13 dataflow + warp->tile permutation {0,3,1,2,7,4,6,5} so each SMSP
// (wid%4) carries exactly 5 phase-B strips instead of up to 6.
__global__ void __launch_bounds__(256, 3)
k_attn_mma(const float* __restrict__ q, const float* __restrict__ k,
           const float* __restrict__ v, const float* __restrict__ nk,
           const float* __restrict__ nv, float* __restrict__ out)
{
    extern __shared__ uint32_t sh[];
    uint32_t* Kh = sh + KHOFF;           // 256 rows x HSTR (fp16 permuted)
    uint32_t* Vh = sh + VHOFF;           // 256 rows x HSTR (fp16 plain)
    uint32_t* Qh = Vh;                   // Q staging reuses V region

    int tid  = threadIdx.x;
    int wid  = tid >> 5, lane = tid & 31;
    int g    = lane >> 2, t = lane & 3;
    int tile = (int)((0x56472130u >> (wid * 4)) & 7u);  // perm {0,3,1,2,7,4,6,5}
    int R0   = tile * 16;
    int i0   = R0 + g, i1 = R0 + g + 8;

    int blk = blockIdx.x, bh = blk >> 6, u = blk & 63, h = bh & 7;
    bool special = (h >= HH);
    bool smask   = special && (u == NB - 1);

    int   selv = g_sel[bh * NB + u];
    float w    = g_wgt[bh * NB + u];
    const float* qb = q + (size_t)bh * T * DH;
    const float* kb = k + (size_t)bh * T * DH;
    const float* vb = v + (size_t)bh * T * DH;

    // ---- stage Q (x0.125, fp16 HPOS-permuted) into V region ----
    for (int idx = tid; idx < 128 * 16; idx += 256) {
        int r = idx >> 4, c0 = (idx & 15) * 4;
        int srcQ = rot_idx(u * BSZ + r, special);
        float4 qq = reinterpret_cast<const float4*>(qb + (size_t)srcQ * DH)[c0 >> 2];
        int p0 = c0 >> 1;
        Qh[r * HSTR + HPOS(p0)]     = pack_h2(qq.x * 0.125f, qq.y * 0.125f);
        Qh[r * HSTR + HPOS(p0 + 1)] = pack_h2(qq.z * 0.125f, qq.w * 0.125f);
    }
    __syncthreads();

    // ---- extract Q A-fragments (4x ld.128) ----
    uint32_t qA0[8], qA1[8];
    {
        uint4 x;
        x = *reinterpret_cast<uint4*>(&Qh[i0 * HSTR + t * 8]);
        qA0[0] = x.x; qA0[1] = x.y; qA0[2] = x.z; qA0[3] = x.w;
        x = *reinterpret_cast<uint4*>(&Qh[i0 * HSTR + t * 8 + 4]);
        qA0[4] = x.x; qA0[5] = x.y; qA0[6] = x.z; qA0[7] = x.w;
        x = *reinterpret_cast<uint4*>(&Qh[i1 * HSTR + t * 8]);
        qA1[0] = x.x; qA1[1] = x.y; qA1[2] = x.z; qA1[3] = x.w;
        x = *reinterpret_cast<uint4*>(&Qh[i1 * HSTR + t * 8 + 4]);
        qA1[4] = x.x; qA1[5] = x.y; qA1[6] = x.z; qA1[7] = x.w;
    }
    __syncthreads();   // Q reads done before V staging overwrites

    // ---- single-burst stage: K (HPOS) + V (plain) fp16, both phases ----
    for (int idx = tid; idx < 256 * 16; idx += 256) {
        int r = idx >> 4, c0 = (idx & 15) * 4;
        float4 kk, vv;
        if (r < 128) {
            if (selv == 0) {
                kk = reinterpret_cast<const float4*>(nk + h * DH)[c0 >> 2];
                vv = reinterpret_cast<const float4*>(nv + h * DH)[c0 >> 2];
            } else {
                int srcA = rot_idx((selv - 1) * BSZ + r, special);
                kk = reinterpret_cast<const float4*>(kb + (size_t)srcA * DH)[c0 >> 2];
                vv = reinterpret_cast<const float4*>(vb + (size_t)srcA * DH)[c0 >> 2];
            }
            kk.x *= w; kk.y *= w; kk.z *= w; kk.w *= w;
            vv.x *= w; vv.y *= w; vv.z *= w; vv.w *= w;
        } else {
            int srcB = rot_idx(u * BSZ + (r - 128), special);
            kk = reinterpret_cast<const float4*>(kb + (size_t)srcB * DH)[c0 >> 2];
            vv = reinterpret_cast<const float4*>(vb + (size_t)srcB * DH)[c0 >> 2];
        }
        int p0 = c0 >> 1;
        Kh[r * HSTR + HPOS(p0)]     = pack_h2(kk.x, kk.y);
        Kh[r * HSTR + HPOS(p0 + 1)] = pack_h2(kk.z, kk.w);
        Vh[r * HSTR + p0]     = pack_h2(vv.x, vv.y);
        Vh[r * HSTR + p0 + 1] = pack_h2(vv.z, vv.w);
    }
    __syncthreads();   // LAST block sync

    float oacc[8][4];
    #pragma unroll
    for (int n = 0; n < 8; ++n)
        #pragma unroll
        for (int m = 0; m < 4; ++m) oacc[n][m] = 0.f;
    float lsum0 = 0.f, lsum1 = 0.f;

    // ldmatrix lane base: tile2 = lane>>3 covers j-offset {0,8,16,24}, row = lane&7
    uint32_t vbase;
    {
        int tl = lane >> 3, rr = lane & 7;
        int joff = (tl & 1) * 8 + (tl >> 1) * 16 + rr;
        vbase = smem_u32(Vh) + (uint32_t)(joff * HSTR * 4);
    }

    #define STRIP(PHASE, S, KB)                                               \
    {                                                                         \
        float c4[4][4];                                                       \
        _Pragma("unroll")                                                     \
        for (int n = 0; n < 4; ++n)                                           \
            _Pragma("unroll")                                                 \
            for (int m = 0; m < 4; ++m) c4[n][m] = 0.f;                       \
        /* QK: S[16,32], fp16 m16n8k16 */                                     \
        _Pragma("unroll")                                                     \
        for (int nt = 0; nt < 4; ++nt) {                                      \
            int j = (KB) + (S) * 32 + nt * 8 + g;                             \
            uint4 f1 = *reinterpret_cast<uint4*>(&Kh[j * HSTR + 8 * t]);      \
            uint4 f2 = *reinterpret_cast<uint4*>(&Kh[j * HSTR + 8 * t + 4]);  \
            mma_f16(c4[nt], qA0[0], qA1[0], qA0[1], qA1[1], f1.x, f1.y);      \
            mma_f16(c4[nt], qA0[2], qA1[2], qA0[3], qA1[3], f1.z, f1.w);      \
            mma_f16(c4[nt], qA0[4], qA1[4], qA0[5], qA1[5], f2.x, f2.y);      \
            mma_f16(c4[nt], qA0[6], qA1[6], qA0[7], qA1[7], f2.z, f2.w);      \
        }                                                                     \
        /* epilogue: mask + exp + row-sums */                                 \
        _Pragma("unroll")                                                     \
        for (int nt = 0; nt < 4; ++nt) {                                      \
            int jb = (S) * 32 + nt * 8 + 2 * t;                               \
            _Pragma("unroll")                                                 \
            for (int m = 0; m < 4; ++m) {                                     \
                int row = (m < 2) ? i0 : i1;                                  \
                int jc  = jb + (m & 1);                                       \
                bool ok;                                                      \
                if ((PHASE) == 0) ok = (!smask) || (row == 0);                \
                else ok = smask ? (row == 0 ? (jc == 0)                       \
                                            : (jc >= 1 && jc <= row))         \
                                : (jc <= row);                                \
                float p = ok ? __expf(fminf(c4[nt][m], 80.f)) : 0.f;          \
                if (m < 2) lsum0 += p; else lsum1 += p;                       \
                c4[nt][m] = p;                                                \
            }                                                                 \
        }                                                                     \
        /* P -> fp16 A fragments (accumulator layout == A layout) */          \
        uint32_t pA[8];                                                       \
        pA[0] = pack_h2(c4[0][0], c4[0][1]); pA[1] = pack_h2(c4[0][2], c4[0][3]); \
        pA[2] = pack_h2(c4[1][0], c4[1][1]); pA[3] = pack_h2(c4[1][2], c4[1][3]); \
        pA[4] = pack_h2(c4[2][0], c4[2][1]); pA[5] = pack_h2(c4[2][2], c4[2][3]); \
        pA[6] = pack_h2(c4[3][0], c4[3][1]); pA[7] = pack_h2(c4[3][2], c4[3][3]); \
        /* PV: O[16,64] += P[16,32] * V[32,64], fp16 via ldmatrix.trans */    \
        uint32_t va = vbase + (uint32_t)(((KB) + (S) * 32) * HSTR * 4);       \
        _Pragma("unroll")                                                     \
        for (int nt = 0; nt < 8; ++nt) {                                      \
            uint32_t b0, b1, b2, b3;                                          \
            ldsm_x4_t(b0, b1, b2, b3, va + nt * 16);                          \
            mma_f16(oacc[nt], pA[0], pA[1], pA[2], pA[3], b0, b1);            \
            mma_f16(oacc[nt], pA[4], pA[5], pA[6], pA[7], b2, b3);            \
        }                                                                     \
    }

    // ---- phase A (routed keys, rows 0-127) ----
    {
        int smaxA = (smask && tile > 0) ? -1 : 3;
        for (int s = 0; s <= smaxA; ++s) STRIP(0, s, 0);
    }
    // ---- phase B (own keys, rows 128-255, triangular) ----
    {
        int smaxB = tile >> 1;
        for (int s = 0; s <= smaxB; ++s) STRIP(1, s, 128);
    }
    #undef STRIP

    // ---- row-sum reduction across the 4 lanes of each row group ----
    lsum0 += __shfl_xor_sync(0xFFFFFFFFu, lsum0, 1);
    lsum0 += __shfl_xor_sync(0xFFFFFFFFu, lsum0, 2);
    lsum1 += __shfl_xor_sync(0xFFFFFFFFu, lsum1, 1);
    lsum1 += __shfl_xor_sync(0xFFFFFFFFu, lsum1, 2);
    float inv0 = 1.0f / lsum0;
    float inv1 = 1.0f / lsum1;

    // ---- write O ----
    int gr0 = rot_idx(u * BSZ + i0, special);
    int gr1 = rot_idx(u * BSZ + i1, special);
    float* op0 = out + ((size_t)bh * T + gr0) * DH;
    float* op1 = out + ((size_t)bh * T + gr1) * DH;
    #pragma unroll
    for (int nt = 0; nt < 8; ++nt) {
        int col = nt * 8 + 2 * t;
        *reinterpret_cast<float2*>(op0 + col) =
            make_float2(oacc[nt][0] * inv0, oacc[nt][1] * inv0);
        *reinterpret_cast<float2*>(op1 + col) =
            make_float2(oacc[nt][2] * inv1, oacc[nt][3] * inv1);
    }
}

// ---------------- launch ----------------
extern "C" void kernel_launch(void* const* d_in, const int* in_sizes, int n_in,
                              void* d_out, int out_size)
{
    (void)in_sizes; (void)n_in; (void)out_size;
    const float* q  = (const float*)d_in[0];
    const float* k  = (const float*)d_in[1];
    const float* v  = (const float*)d_in[2];
    const float* nk = (const float*)d_in[3];
    const float* nv = (const float*)d_in[4];
    float* out = (float*)d_out;

    const int smem_attn = SMEM_B32 * 4;          // 73728 B
    const int smem_k2   = K2_SMEM_F * 4;         // 52224 B
    cudaFuncSetAttribute(k_attn_mma, cudaFuncAttributeMaxDynamicSharedMemorySize, smem_attn);
    cudaFuncSetAttribute(k_route2,   cudaFuncAttributeMaxDynamicSharedMemorySize, smem_k2);

    k_bucket_stats<<<BH * NB, 256>>>(q, k);
    k_route2<<<BH, 256, smem_k2>>>();
    k_attn_mma<<<BH * NB, 256, smem_attn>>>(q, k, v, nk, nv, out);
}

// round 17
// speedup vs baseline: 1.1477x; 1.0265x over previous
#include <cuda_runtime.h>
#include <cuda_fp16.h>
#include <cstdint>

#define BH  32
#define T   8192
#define DH  64
#define BSZ 128
#define NB  64
#define HH  4

// ---------------- scratch ----------------
__device__ float g_qsum  [BH*NB*DH];
__device__ float g_ksum  [BH*NB*DH];
__device__ float g_W     [BH*NB*DH];
__device__ float g_qfirst[BH*NB*DH];
__device__ int   g_sel   [BH*NB];
__device__ float g_wgt   [BH*NB];

__device__ __forceinline__ int rot_idx(int g, bool special) {
    return special ? ((g + BSZ - 1) & (T - 1)) : g;
}
__device__ __forceinline__ uint32_t pack_h2(float a, float b) {
    __half2 h = __floats2half2_rn(a, b);
    return *reinterpret_cast<uint32_t*>(&h);
}
__device__ __forceinline__ uint32_t smem_u32(const void* p) {
    uint32_t a;
    asm("{ .reg .u64 t; cvta.to.shared.u64 t, %1; cvt.u32.u64 %0, t; }"
        : "=r"(a) : "l"(p));
    return a;
}
__device__ __forceinline__ void mma_f16(float c[4], uint32_t a0, uint32_t a1,
                                        uint32_t a2, uint32_t a3,
                                        uint32_t b0, uint32_t b1) {
    asm("mma.sync.aligned.m16n8k16.row.col.f32.f16.f16.f32 "
        "{%0,%1,%2,%3}, {%4,%5,%6,%7}, {%8,%9}, {%0,%1,%2,%3};"
        : "+f"(c[0]), "+f"(c[1]), "+f"(c[2]), "+f"(c[3])
        : "r"(a0), "r"(a1), "r"(a2), "r"(a3), "r"(b0), "r"(b1));
}
__device__ __forceinline__ void ldsm_x4_t(uint32_t& r0, uint32_t& r1,
                                          uint32_t& r2, uint32_t& r3,
                                          uint32_t addr) {
    asm volatile("ldmatrix.sync.aligned.m8n8.x4.trans.shared.b16 "
                 "{%0,%1,%2,%3}, [%4];"
                 : "=r"(r0), "=r"(r1), "=r"(r2), "=r"(r3) : "r"(addr));
}

// half2-pair permuted position for K (vectorized QK B fetch)
#define HPOS(p) ((((p) & 3) * 8) + ((p) >> 2))
#define HSTR 36                         // b32 per fp16 row (32 + 4 pad)
#define KHOFF 0
#define VHOFF (256 * HSTR)              // 9216 b32
#define SMEM_B32 (512 * HSTR)           // 18432 b32 = 73728 B

// ---------------- K1: per-bucket stats, float2 loads, 8 segments ----------
// W = sum_j prefix_k(j)*rinv(j) = sum_s [ wl_s + R_before_s * hq_s ]
__global__ void __launch_bounds__(256)
k_bucket_stats(const float* __restrict__ q, const float* __restrict__ k)
{
    __shared__ float rinv[BSZ];
    __shared__ float s_sq[8][DH];
    __shared__ float s_rk[8][DH];
    __shared__ float s_wl[8][DH];
    __shared__ float s_hq[8];
    int blk = blockIdx.x;          // bh*NB + u
    int bh = blk >> 6, u = blk & 63;
    int tx = threadIdx.x;          // 0..255
    int d2 = tx & 31, seg = tx >> 5;   // dims (2*d2, 2*d2+1), j-segment of 16
    bool special = ((bh & 7) >= HH);
    const float* qb = q + (size_t)bh * T * DH;
    const float* kb = k + (size_t)bh * T * DH;
    int base = u * BSZ;

    if (tx < BSZ) rinv[tx] = 1.0f / (float)(base + tx + 1);
    __syncthreads();

    float2 sumq = make_float2(0.f, 0.f);
    float2 rk   = make_float2(0.f, 0.f);
    float2 wl   = make_float2(0.f, 0.f);
    float  hq   = 0.f;
    float2 qfirst = make_float2(0.f, 0.f);
    int j0 = seg * 16;
    #pragma unroll 8
    for (int jj = 0; jj < 16; ++jj) {
        int j = j0 + jj;
        int src = rot_idx(base + j, special);
        float2 qv = *reinterpret_cast<const float2*>(qb + (size_t)src * DH + 2 * d2);
        float2 kv = *reinterpret_cast<const float2*>(kb + (size_t)src * DH + 2 * d2);
        if (seg == 0 && jj == 0) qfirst = qv;
        sumq.x += qv.x; sumq.y += qv.y;
        rk.x   += kv.x; rk.y   += kv.y;
        float ri = rinv[j];
        wl.x = fmaf(rk.x, ri, wl.x);
        wl.y = fmaf(rk.y, ri, wl.y);
        hq += ri;
    }
    s_sq[seg][2 * d2] = sumq.x; s_sq[seg][2 * d2 + 1] = sumq.y;
    s_rk[seg][2 * d2] = rk.x;   s_rk[seg][2 * d2 + 1] = rk.y;
    s_wl[seg][2 * d2] = wl.x;   s_wl[seg][2 * d2 + 1] = wl.y;
    if (d2 == 0) s_hq[seg] = hq;
    if (seg == 0) {
        int o = blk * DH + 2 * d2;
        g_qfirst[o] = qfirst.x; g_qfirst[o + 1] = qfirst.y;
    }
    __syncthreads();

    if (tx < DH) {
        int d = tx;
        float R = 0.f, W = 0.f, SQ = 0.f;
        #pragma unroll
        for (int s = 0; s < 8; ++s) {
            W = fmaf(R, s_hq[s], W + s_wl[s][d]);
            R += s_rk[s][d];
            SQ += s_sq[s][d];
        }
        int o = blk * DH + d;
        g_qsum[o] = SQ; g_ksum[o] = R; g_W[o] = W;
    }
}

// ---------------- K2: parallel prefix + routing (256 thr/bh) ----------------
#define K2_SQ  0
#define K2_SK  4160
#define K2_LG  8320
#define K2_H   12480
#define K2_GQ  12544
#define K2_GK  12800
#define K2_SMEM_F 13056

__global__ void __launch_bounds__(256)
k_route2()
{
    extern __shared__ float s2[];
    int bh = blockIdx.x;
    int tx = threadIdx.x;
    int d  = tx & 63, qd = tx >> 6;

    if (qd == 0) {             // H[u]
        int u = d;
        float hsum = 0.f;
        for (int j = 1; j <= BSZ; ++j) hsum += 1.0f / (float)(u * BSZ + j);
        s2[K2_H + u] = hsum;
    }

    // segment sums (buckets [16qd, 16qd+16))
    float sq_ = 0.f, sk_ = 0.f;
    #pragma unroll 4
    for (int i = 0; i < 16; ++i) {
        int o = (bh * NB + qd * 16 + i) * DH + d;
        sq_ += g_qsum[o]; sk_ += g_ksum[o];
    }
    s2[K2_GQ + qd * 64 + d] = sq_;
    s2[K2_GK + qd * 64 + d] = sk_;
    __syncthreads();

    float baseQ = 0.f, baseK = 0.f;
    for (int q2 = 0; q2 < qd; ++q2) {
        baseQ += s2[K2_GQ + q2 * 64 + d];
        baseK += s2[K2_GK + q2 * 64 + d];
    }
    for (int i = 0; i < 16; ++i) {
        int uu = qd * 16 + i;
        int o = (bh * NB + uu) * DH + d;
        s2[K2_SQ + uu * 65 + d] = (baseQ + g_qfirst[o]) / (float)(uu * BSZ + 1);
        s2[K2_SK + uu * 65 + d] = baseK * s2[K2_H + uu] + g_W[o];
        baseQ += g_qsum[o]; baseK += g_ksum[o];
    }
    __syncthreads();

    // logits: thread (u=d, qd) handles vv in {1+qd, 5+qd, ...} <= u
    {
        int u = d;
        if (qd == 0) s2[K2_LG + u * 65] = 0.f;   // null column
        const float* squ = s2 + K2_SQ + u * 65;
        for (int vv = 1 + qd; vv <= u; vv += 4) {
            const float* skv = s2 + K2_SK + (vv - 1) * 65;
            float s = 0.f;
            #pragma unroll 8
            for (int dd = 0; dd < DH; ++dd) s += squ[dd] * skv[dd];
            s2[K2_LG + u * 65 + vv] = s * 0.125f;
        }
    }
    __syncthreads();

    // scan: one thread per u
    if (tx < NB) {
        int u = tx;
        if (u == 0) { g_sel[bh * NB] = 0; g_wgt[bh * NB] = 0.f; return; }
        const float* lg = s2 + K2_LG + u * 65;
        float m = 0.f;
        for (int vv = 1; vv <= u; ++vv) m = fmaxf(m, lg[vv]);
        float ssum = expf(0.f - m);
        for (int vv = 1; vv <= u; ++vv) ssum += expf(lg[vv] - m);
        int best = 0; float bl = lg[0];
        for (int vv = 1; vv <= u - 1; ++vv)
            if (lg[vv] > bl) { bl = lg[vv]; best = vv; }
        g_sel[bh * NB + u] = best;
        g_wgt[bh * NB + u] = expf(bl - m) / ssum;
    }
}

// ---------------- K4: full-fp16 MMA attention tile (v7 = R13 exact) --------
__global__ void __launch_bounds__(256, 3)
k_attn_mma(const float* __restrict__ q, const float* __restrict__ k,
           const float* __restrict__ v, const float* __restrict__ nk,
           const float* __restrict__ nv, float* __restrict__ out)
{
    extern __shared__ uint32_t sh[];
    uint32_t* Kh = sh + KHOFF;           // 256 rows x HSTR (fp16 permuted)
    uint32_t* Vh = sh + VHOFF;           // 256 rows x HSTR (fp16 plain)
    uint32_t* Qh = Vh;                   // Q staging reuses V region

    int tid  = threadIdx.x;
    int wid  = tid >> 5, lane = tid & 31;
    int g    = lane >> 2, t = lane & 3;
    int R0   = wid * 16;
    int i0   = R0 + g, i1 = R0 + g + 8;

    int blk = blockIdx.x, bh = blk >> 6, u = blk & 63, h = bh & 7;
    bool special = (h >= HH);
    bool smask   = special && (u == NB - 1);

    int   selv = g_sel[bh * NB + u];
    float w    = g_wgt[bh * NB + u];
    const float* qb = q + (size_t)bh * T * DH;
    const float* kb = k + (size_t)bh * T * DH;
    const float* vb = v + (size_t)bh * T * DH;

    // ---- stage Q (x0.125, fp16 HPOS-permuted) into V region ----
    for (int idx = tid; idx < 128 * 16; idx += 256) {
        int r = idx >> 4, c0 = (idx & 15) * 4;
        int srcQ = rot_idx(u * BSZ + r, special);
        float4 qq = reinterpret_cast<const float4*>(qb + (size_t)srcQ * DH)[c0 >> 2];
        int p0 = c0 >> 1;
        Qh[r * HSTR + HPOS(p0)]     = pack_h2(qq.x * 0.125f, qq.y * 0.125f);
        Qh[r * HSTR + HPOS(p0 + 1)] = pack_h2(qq.z * 0.125f, qq.w * 0.125f);
    }
    __syncthreads();

    // ---- extract Q A-fragments (4x ld.128) ----
    uint32_t qA0[8], qA1[8];
    {
        uint4 x;
        x = *reinterpret_cast<uint4*>(&Qh[i0 * HSTR + t * 8]);
        qA0[0] = x.x; qA0[1] = x.y; qA0[2] = x.z; qA0[3] = x.w;
        x = *reinterpret_cast<uint4*>(&Qh[i0 * HSTR + t * 8 + 4]);
        qA0[4] = x.x; qA0[5] = x.y; qA0[6] = x.z; qA0[7] = x.w;
        x = *reinterpret_cast<uint4*>(&Qh[i1 * HSTR + t * 8]);
        qA1[0] = x.x; qA1[1] = x.y; qA1[2] = x.z; qA1[3] = x.w;
        x = *reinterpret_cast<uint4*>(&Qh[i1 * HSTR + t * 8 + 4]);
        qA1[4] = x.x; qA1[5] = x.y; qA1[6] = x.z; qA1[7] = x.w;
    }
    __syncthreads();   // Q reads done before V staging overwrites

    // ---- single-burst stage: K (HPOS) + V (plain) fp16, both phases ----
    for (int idx = tid; idx < 256 * 16; idx += 256) {
        int r = idx >> 4, c0 = (idx & 15) * 4;
        float4 kk, vv;
        if (r < 128) {
            if (selv == 0) {
                kk = reinterpret_cast<const float4*>(nk + h * DH)[c0 >> 2];
                vv = reinterpret_cast<const float4*>(nv + h * DH)[c0 >> 2];
            } else {
                int srcA = rot_idx((selv - 1) * BSZ + r, special);
                kk = reinterpret_cast<const float4*>(kb + (size_t)srcA * DH)[c0 >> 2];
                vv = reinterpret_cast<const float4*>(vb + (size_t)srcA * DH)[c0 >> 2];
            }
            kk.x *= w; kk.y *= w; kk.z *= w; kk.w *= w;
            vv.x *= w; vv.y *= w; vv.z *= w; vv.w *= w;
        } else {
            int srcB = rot_idx(u * BSZ + (r - 128), special);
            kk = reinterpret_cast<const float4*>(kb + (size_t)srcB * DH)[c0 >> 2];
            vv = reinterpret_cast<const float4*>(vb + (size_t)srcB * DH)[c0 >> 2];
        }
        int p0 = c0 >> 1;
        Kh[r * HSTR + HPOS(p0)]     = pack_h2(kk.x, kk.y);
        Kh[r * HSTR + HPOS(p0 + 1)] = pack_h2(kk.z, kk.w);
        Vh[r * HSTR + p0]     = pack_h2(vv.x, vv.y);
        Vh[r * HSTR + p0 + 1] = pack_h2(vv.z, vv.w);
    }
    __syncthreads();   // LAST block sync

    float oacc[8][4];
    #pragma unroll
    for (int n = 0; n < 8; ++n)
        #pragma unroll
        for (int m = 0; m < 4; ++m) oacc[n][m] = 0.f;
    float lsum0 = 0.f, lsum1 = 0.f;

    // ldmatrix lane base: tile = lane>>3 covers j-offset {0,8,16,24}, row = lane&7
    uint32_t vbase;
    {
        int tile = lane >> 3, rr = lane & 7;
        int joff = (tile & 1) * 8 + (tile >> 1) * 16 + rr;
        vbase = smem_u32(Vh) + (uint32_t)(joff * HSTR * 4);
    }

    #define STRIP(PHASE, S, KB)                                               \
    {                                                                         \
        float c4[4][4];                                                       \
        _Pragma("unroll")                                                     \
        for (int n = 0; n < 4; ++n)                                           \
            _Pragma("unroll")                                                 \
            for (int m = 0; m < 4; ++m) c4[n][m] = 0.f;                       \
        /* QK: S[16,32], fp16 m16n8k16 */                                     \
        _Pragma("unroll")                                                     \
        for (int nt = 0; nt < 4; ++nt) {                                      \
            int j = (KB) + (S) * 32 + nt * 8 + g;                             \
            uint4 f1 = *reinterpret_cast<uint4*>(&Kh[j * HSTR + 8 * t]);      \
            uint4 f2 = *reinterpret_cast<uint4*>(&Kh[j * HSTR + 8 * t + 4]);  \
            mma_f16(c4[nt], qA0[0], qA1[0], qA0[1], qA1[1], f1.x, f1.y);      \
            mma_f16(c4[nt], qA0[2], qA1[2], qA0[3], qA1[3], f1.z, f1.w);      \
            mma_f16(c4[nt], qA0[4], qA1[4], qA0[5], qA1[5], f2.x, f2.y);      \
            mma_f16(c4[nt], qA0[6], qA1[6], qA0[7], qA1[7], f2.z, f2.w);      \
        }                                                                     \
        /* epilogue: mask + exp + row-sums */                                 \
        _Pragma("unroll")                                                     \
        for (int nt = 0; nt < 4; ++nt) {                                      \
            int jb = (S) * 32 + nt * 8 + 2 * t;                               \
            _Pragma("unroll")                                                 \
            for (int m = 0; m < 4; ++m) {                                     \
                int row = (m < 2) ? i0 : i1;                                  \
                int jc  = jb + (m & 1);                                       \
                bool ok;                                                      \
                if ((PHASE) == 0) ok = (!smask) || (row == 0);                \
                else ok = smask ? (row == 0 ? (jc == 0)                       \
                                            : (jc >= 1 && jc <= row))         \
                                : (jc <= row);                                \
                float p = ok ? __expf(fminf(c4[nt][m], 80.f)) : 0.f;          \
                if (m < 2) lsum0 += p; else lsum1 += p;                       \
                c4[nt][m] = p;                                                \
            }                                                                 \
        }                                                                     \
        /* P -> fp16 A fragments (accumulator layout == A layout) */          \
        uint32_t pA[8];                                                       \
        pA[0] = pack_h2(c4[0][0], c4[0][1]); pA[1] = pack_h2(c4[0][2], c4[0][3]); \
        pA[2] = pack_h2(c4[1][0], c4[1][1]); pA[3] = pack_h2(c4[1][2], c4[1][3]); \
        pA[4] = pack_h2(c4[2][0], c4[2][1]); pA[5] = pack_h2(c4[2][2], c4[2][3]); \
        pA[6] = pack_h2(c4[3][0], c4[3][1]); pA[7] = pack_h2(c4[3][2], c4[3][3]); \
        /* PV: O[16,64] += P[16,32] * V[32,64], fp16 via ldmatrix.trans */    \
        uint32_t va = vbase + (uint32_t)(((KB) + (S) * 32) * HSTR * 4);       \
        _Pragma("unroll")                                                     \
        for (int nt = 0; nt < 8; ++nt) {                                      \
            uint32_t b0, b1, b2, b3;                                          \
            ldsm_x4_t(b0, b1, b2, b3, va + nt * 16);                          \
            mma_f16(oacc[nt], pA[0], pA[1], pA[2], pA[3], b0, b1);            \
            mma_f16(oacc[nt], pA[4], pA[5], pA[6], pA[7], b2, b3);            \
        }                                                                     \
    }

    // ---- phase A (routed keys, rows 0-127) ----
    {
        int smaxA = (smask && wid > 0) ? -1 : 3;
        for (int s = 0; s <= smaxA; ++s) STRIP(0, s, 0);
    }
    // ---- phase B (own keys, rows 128-255, triangular) ----
    {
        int smaxB = (R0 + 15) >> 5;
        for (int s = 0; s <= smaxB; ++s) STRIP(1, s, 128);
    }
    #undef STRIP

    // ---- row-sum reduction across the 4 lanes of each row group ----
    lsum0 += __shfl_xor_sync(0xFFFFFFFFu, lsum0, 1);
    lsum0 += __shfl_xor_sync(0xFFFFFFFFu, lsum0, 2);
    lsum1 += __shfl_xor_sync(0xFFFFFFFFu, lsum1, 1);
    lsum1 += __shfl_xor_sync(0xFFFFFFFFu, lsum1, 2);
    float inv0 = 1.0f / lsum0;
    float inv1 = 1.0f / lsum1;

    // ---- write O ----
    int gr0 = rot_idx(u * BSZ + i0, special);
    int gr1 = rot_idx(u * BSZ + i1, special);
    float* op0 = out + ((size_t)bh * T + gr0) * DH;
    float* op1 = out + ((size_t)bh * T + gr1) * DH;
    #pragma unroll
    for (int nt = 0; nt < 8; ++nt) {
        int col = nt * 8 + 2 * t;
        *reinterpret_cast<float2*>(op0 + col) =
            make_float2(oacc[nt][0] * inv0, oacc[nt][1] * inv0);
        *reinterpret_cast<float2*>(op1 + col) =
            make_float2(oacc[nt][2] * inv1, oacc[nt][3] * inv1);
    }
}

// ---------------- launch ----------------
extern "C" void kernel_launch(void* const* d_in, const int* in_sizes, int n_in,
                              void* d_out, int out_size)
{
    (void)in_sizes; (void)n_in; (void)out_size;
    const float* q  = (const float*)d_in[0];
    const float* k  = (const float*)d_in[1];
    const float* v  = (const float*)d_in[2];
    const float* nk = (const float*)d_in[3];
    const float* nv = (const float*)d_in[4];
    float* out = (float*)d_out;

    const int smem_attn = SMEM_B32 * 4;          // 73728 B
    const int smem_k2   = K2_SMEM_F * 4;         // 52224 B
    cudaFuncSetAttribute(k_attn_mma, cudaFuncAttributeMaxDynamicSharedMemorySize, smem_attn);
    cudaFuncSetAttribute(k_route2,   cudaFuncAttributeMaxDynamicSharedMemorySize, smem_k2);

    k_bucket_stats<<<BH * NB, 256>>>(q, k);
    k_route2<<<BH, 256, smem_k2>>>();
    k_attn_mma<<<BH * NB, 256, smem_attn>>>(q, k, v, nk, nv, out);
}